// round 3
// baseline (speedup 1.0000x reference)
#include <cuda_runtime.h>
#include <cuda_bf16.h>
#include <math.h>

// Problem constants (match reference)
#define NN      50000
#define EE      600000
#define D_IN    128
#define D_H     128
#define D_OUT   64
#define NLAYERS 3
#define NG      64
#define SLOPE   0.2f

// ---------------------------------------------------------------------------
// Device scratch (no allocations allowed)
// ---------------------------------------------------------------------------
__device__ __align__(16) float g_h [NN * D_H];   // node features (updated in place per layer)
__device__ __align__(16) float g_hp[NN * D_H];   // h @ Wg
__device__ float g_es[NN];
__device__ float g_ed[NN];
__device__ int   g_deg[NN];
__device__ int   g_off[NN + 1];
__device__ int   g_cur[NN];
__device__ int   g_csrc[EE];                     // CSR by dst: source node ids
__device__ __align__(16) float g_pooled[NG * D_H];
__device__ int   g_is64;                         // runtime index-dtype flag

__device__ __forceinline__ float leaky(float x) {
    return x >= 0.f ? x : SLOPE * x;
}

// Load index i from a buffer that is either int32 or int64, per g_is64.
__device__ __forceinline__ int load_idx(const void* p, long long i) {
    return g_is64 ? (int)((const long long*)p)[i] : ((const int*)p)[i];
}

// ---------------------------------------------------------------------------
// Index dtype detection: for int64 node ids (< 50000) every odd 32-bit word
// is zero; for int32 they are random node ids (essentially never all zero).
// ---------------------------------------------------------------------------
__global__ void k_detect(const int* __restrict__ eiw) {
    if (threadIdx.x == 0 && blockIdx.x == 0) {
        int is64 = 1;
        #pragma unroll 1
        for (int i = 0; i < 64; i++) {
            if (eiw[2 * i + 1] != 0) { is64 = 0; break; }
        }
        g_is64 = is64;
    }
}

// ---------------------------------------------------------------------------
// CSR build
// ---------------------------------------------------------------------------
__global__ void k_zero_deg() {
    int i = blockIdx.x * blockDim.x + threadIdx.x;
    if (i < NN) g_deg[i] = 0;
}

__global__ void k_hist(const void* __restrict__ ei) {
    int e = blockIdx.x * blockDim.x + threadIdx.x;
    if (e < EE) {
        int d = load_idx(ei, (long long)EE + e);
        if ((unsigned)d < NN) atomicAdd(&g_deg[d], 1);
    }
}

// single-block scan over 50000 ints
__global__ void k_scan() {
    __shared__ int sm[1024];
    __shared__ int carry;
    int tid = threadIdx.x;
    if (tid == 0) { carry = 0; g_off[0] = 0; }
    __syncthreads();
    for (int base = 0; base < NN; base += 1024) {
        int i = base + tid;
        int v = (i < NN) ? g_deg[i] : 0;
        sm[tid] = v;
        __syncthreads();
        #pragma unroll
        for (int s = 1; s < 1024; s <<= 1) {
            int t = (tid >= s) ? sm[tid - s] : 0;
            __syncthreads();
            sm[tid] += t;
            __syncthreads();
        }
        int inc = carry + sm[tid];        // inclusive prefix
        if (i < NN) {
            g_off[i + 1] = inc;
            g_cur[i] = inc - v;           // exclusive prefix = running cursor
        }
        __syncthreads();
        if (tid == 0) carry += sm[1023];
        __syncthreads();
    }
}

__global__ void k_scatter(const void* __restrict__ ei) {
    int e = blockIdx.x * blockDim.x + threadIdx.x;
    if (e < EE) {
        int s = load_idx(ei, e);
        int d = load_idx(ei, (long long)EE + e);
        if ((unsigned)d < NN && (unsigned)s < NN) {
            int pos = atomicAdd(&g_cur[d], 1);
            g_csrc[pos] = s;
        }
    }
}

// ---------------------------------------------------------------------------
// SGEMM core: C[M,128] = A[M,128] @ B[128,128] (+bias)
// BM=64, BN=128, BK=16; 256 threads; thread tile 4x8
// ---------------------------------------------------------------------------
__device__ __forceinline__ void sgemm128_body(const float* __restrict__ A,
                                              const float* __restrict__ B,
                                              const float* __restrict__ bias,
                                              float* __restrict__ C, int M) {
    __shared__ __align__(16) float As[16][64];
    __shared__ __align__(16) float Bs[16][128];
    const int tid = threadIdx.x;
    const int brow = blockIdx.x * 64;
    const int tx = tid & 15;          // col group 0..15 -> cols tx*8..tx*8+7
    const int ty = tid >> 4;          // row group 0..15 -> rows ty*4..ty*4+3

    const int ar = tid >> 2;          // 0..63 row within tile
    const int ak = (tid & 3) * 4;     // 0,4,8,12 k chunk
    const int bk = tid >> 5;          // 0..7
    const int bc = (tid & 31) * 4;    // 0..124

    float acc[4][8];
    #pragma unroll
    for (int r = 0; r < 4; r++)
        #pragma unroll
        for (int c = 0; c < 8; c++) acc[r][c] = 0.f;

    for (int k0 = 0; k0 < 128; k0 += 16) {
        int grow = brow + ar;
        float4 av = (grow < M) ? *(const float4*)&A[(size_t)grow * 128 + k0 + ak]
                               : make_float4(0.f, 0.f, 0.f, 0.f);
        As[ak + 0][ar] = av.x;
        As[ak + 1][ar] = av.y;
        As[ak + 2][ar] = av.z;
        As[ak + 3][ar] = av.w;
        *(float4*)&Bs[bk][bc]     = *(const float4*)&B[(k0 + bk) * 128 + bc];
        *(float4*)&Bs[bk + 8][bc] = *(const float4*)&B[(k0 + bk + 8) * 128 + bc];
        __syncthreads();

        #pragma unroll
        for (int k = 0; k < 16; k++) {
            float4 a4 = *(const float4*)&As[k][ty * 4];
            float4 b0 = *(const float4*)&Bs[k][tx * 8];
            float4 b1 = *(const float4*)&Bs[k][tx * 8 + 4];
            float av_[4] = {a4.x, a4.y, a4.z, a4.w};
            float bv_[8] = {b0.x, b0.y, b0.z, b0.w, b1.x, b1.y, b1.z, b1.w};
            #pragma unroll
            for (int r = 0; r < 4; r++)
                #pragma unroll
                for (int c = 0; c < 8; c++)
                    acc[r][c] = fmaf(av_[r], bv_[c], acc[r][c]);
        }
        __syncthreads();
    }

    float bv[8];
    #pragma unroll
    for (int c = 0; c < 8; c++) bv[c] = bias ? bias[tx * 8 + c] : 0.f;

    #pragma unroll
    for (int r = 0; r < 4; r++) {
        int row = brow + ty * 4 + r;
        if (row < M) {
            float4 o0, o1;
            o0.x = acc[r][0] + bv[0]; o0.y = acc[r][1] + bv[1];
            o0.z = acc[r][2] + bv[2]; o0.w = acc[r][3] + bv[3];
            o1.x = acc[r][4] + bv[4]; o1.y = acc[r][5] + bv[5];
            o1.z = acc[r][6] + bv[6]; o1.w = acc[r][7] + bv[7];
            *(float4*)&C[(size_t)row * 128 + tx * 8]     = o0;
            *(float4*)&C[(size_t)row * 128 + tx * 8 + 4] = o1;
        }
    }
}

// mlp1: g_h = x @ W1 + b1
__global__ void k_sgemm_x(const float* __restrict__ A,
                          const float* __restrict__ B,
                          const float* __restrict__ bias) {
    sgemm128_body(A, B, bias, g_h, NN);
}

// per-layer: g_hp = g_h @ Wg[l]   (no bias)
__global__ void k_sgemm_h(const float* __restrict__ B) {
    sgemm128_body(g_h, B, nullptr, g_hp, NN);
}

// ---------------------------------------------------------------------------
// es/ed: per-node dot products hp . a_src, hp . a_dst  (warp per node)
// ---------------------------------------------------------------------------
__global__ void k_esed(const float* __restrict__ asrc,
                       const float* __restrict__ adst) {
    int warp = (blockIdx.x * blockDim.x + threadIdx.x) >> 5;
    int lane = threadIdx.x & 31;
    if (warp >= NN) return;
    const float4* hp4 = (const float4*)g_hp;
    float4 v = hp4[(size_t)warp * 32 + lane];
    float4 a = ((const float4*)asrc)[lane];
    float4 b = ((const float4*)adst)[lane];
    float ps = v.x * a.x + v.y * a.y + v.z * a.z + v.w * a.w;
    float pd = v.x * b.x + v.y * b.y + v.z * b.z + v.w * b.w;
    #pragma unroll
    for (int o = 16; o; o >>= 1) {
        ps += __shfl_xor_sync(0xffffffffu, ps, o);
        pd += __shfl_xor_sync(0xffffffffu, pd, o);
    }
    if (lane == 0) {
        g_es[warp] = ps;
        g_ed[warp] = pd;
    }
}

// ---------------------------------------------------------------------------
// GAT aggregation (warp per destination node): segment softmax + weighted
// gather + bias + relu + residual, all fused. Writes g_h in place.
// ---------------------------------------------------------------------------
__global__ void k_gat_aggr(const float* __restrict__ bg) {
    int warp = (blockIdx.x * blockDim.x + threadIdx.x) >> 5;
    int lane = threadIdx.x & 31;
    if (warp >= NN) return;
    const int d = warp;
    const int lo = g_off[d], hi = g_off[d + 1];
    const float es_d = g_es[d], ed_d = g_ed[d];
    const float e_self = leaky(es_d + ed_d);

    // segment max (self-loop included)
    float m = e_self;
    for (int j = lo + lane; j < hi; j += 32) {
        int s = g_csrc[j];
        m = fmaxf(m, leaky(g_es[s] + ed_d));
    }
    #pragma unroll
    for (int o = 16; o; o >>= 1) m = fmaxf(m, __shfl_xor_sync(0xffffffffu, m, o));

    // segment sum of exp
    float z = 0.f;
    for (int j = lo + lane; j < hi; j += 32) {
        int s = g_csrc[j];
        z += expf(leaky(g_es[s] + ed_d) - m);
    }
    #pragma unroll
    for (int o = 16; o; o >>= 1) z += __shfl_xor_sync(0xffffffffu, z, o);
    z += expf(e_self - m);
    const float invz = 1.0f / z;

    const float4* hp4 = (const float4*)g_hp;
    float4* h4 = (float4*)g_h;

    // self-loop contribution
    float a_self = expf(e_self - m) * invz;
    float4 v = hp4[(size_t)d * 32 + lane];
    float4 acc;
    acc.x = a_self * v.x; acc.y = a_self * v.y;
    acc.z = a_self * v.z; acc.w = a_self * v.w;

    // in-edges: serial over edges, lanes cover feature dim (float4 x 32 = 128)
    for (int j = lo; j < hi; ++j) {
        int s = g_csrc[j];                                  // broadcast load
        float a = expf(leaky(g_es[s] + ed_d) - m) * invz;   // per-lane recompute (cheap)
        float4 w = hp4[(size_t)s * 32 + lane];
        acc.x = fmaf(a, w.x, acc.x);
        acc.y = fmaf(a, w.y, acc.y);
        acc.z = fmaf(a, w.z, acc.z);
        acc.w = fmaf(a, w.w, acc.w);
    }

    // + bias, relu, residual
    float4 b = ((const float4*)bg)[lane];
    float4 hin = h4[(size_t)d * 32 + lane];
    float4 o;
    o.x = fmaxf(acc.x + b.x, 0.f) + hin.x;
    o.y = fmaxf(acc.y + b.y, 0.f) + hin.y;
    o.z = fmaxf(acc.z + b.z, 0.f) + hin.z;
    o.w = fmaxf(acc.w + b.w, 0.f) + hin.w;
    h4[(size_t)d * 32 + lane] = o;
}

// ---------------------------------------------------------------------------
// Global add pool: batch is sorted; one block per graph, binary search range.
// ---------------------------------------------------------------------------
__global__ void k_pool(const void* __restrict__ batch) {
    __shared__ int s_lo, s_hi;
    const int g = blockIdx.x;
    const int tid = threadIdx.x; // 0..127 = feature column
    if (tid == 0) {
        int lo = 0, hi = NN;
        while (lo < hi) { int mid = (lo + hi) >> 1; if (load_idx(batch, mid) < g) lo = mid + 1; else hi = mid; }
        s_lo = lo;
        lo = 0; hi = NN;
        int g1 = g + 1;
        while (lo < hi) { int mid = (lo + hi) >> 1; if (load_idx(batch, mid) < g1) lo = mid + 1; else hi = mid; }
        s_hi = lo;
    }
    __syncthreads();
    float acc = 0.f;
    for (int i = s_lo; i < s_hi; ++i) acc += g_h[(size_t)i * 128 + tid];
    g_pooled[g * 128 + tid] = acc;
}

// out[g, o] = b2[o] + sum_k pooled[g,k] * W2[k,o]
__global__ void k_final(const float* __restrict__ W2,
                        const float* __restrict__ b2,
                        float* __restrict__ out) {
    const int g = blockIdx.x;   // 0..63
    const int o = threadIdx.x;  // 0..63
    float acc = b2[o];
    #pragma unroll 8
    for (int k = 0; k < 128; ++k)
        acc = fmaf(g_pooled[g * 128 + k], W2[k * 64 + o], acc);
    out[g * 64 + o] = acc;
}

// ---------------------------------------------------------------------------
// Launch (kernel launches only — fully graph-capturable)
// ---------------------------------------------------------------------------
extern "C" void kernel_launch(void* const* d_in, const int* in_sizes, int n_in,
                              void* d_out, int out_size) {
    const float* x     = (const float*)d_in[0];
    const void*  ei    = d_in[1];
    const void*  batch = d_in[2];
    const float* W1    = (const float*)d_in[3];
    const float* b1    = (const float*)d_in[4];
    const float* Wg    = (const float*)d_in[5];
    const float* asrc  = (const float*)d_in[6];
    const float* adst  = (const float*)d_in[7];
    const float* bg    = (const float*)d_in[8];
    const float* W2    = (const float*)d_in[9];
    const float* b2    = (const float*)d_in[10];
    float*       out   = (float*)d_out;

    // index dtype detection, then CSR build
    k_detect<<<1, 32>>>((const int*)ei);
    k_zero_deg<<<(NN + 255) / 256, 256>>>();
    k_hist<<<(EE + 255) / 256, 256>>>(ei);
    k_scan<<<1, 1024>>>();
    k_scatter<<<(EE + 255) / 256, 256>>>(ei);

    const int gemm_blocks = (NN + 63) / 64;
    const int node_warp_blocks = (NN * 32 + 255) / 256;

    // mlp1: h = x @ W1 + b1
    k_sgemm_x<<<gemm_blocks, 256>>>(x, W1, b1);

    for (int l = 0; l < NLAYERS; ++l) {
        k_sgemm_h<<<gemm_blocks, 256>>>(Wg + (size_t)l * 128 * 128);
        k_esed<<<node_warp_blocks, 256>>>(asrc + l * 128, adst + l * 128);
        k_gat_aggr<<<node_warp_blocks, 256>>>(bg + l * 128);
    }

    k_pool<<<NG, 128>>>(batch);
    k_final<<<NG, 64>>>(W2, b2, out);
}

// round 4
// speedup vs baseline: 1.1292x; 1.1292x over previous
#include <cuda_runtime.h>
#include <cuda_bf16.h>
#include <math.h>

// Problem constants (match reference)
#define NN      50000
#define EE      600000
#define D_IN    128
#define D_H     128
#define D_OUT   64
#define NLAYERS 3
#define NG      64
#define SLOPE   0.2f

// ---------------------------------------------------------------------------
// Device scratch (no allocations allowed)
// ---------------------------------------------------------------------------
__device__ __align__(16) float g_h [NN * D_H];   // node features (updated in place per layer)
__device__ __align__(16) float g_hp[NN * D_H];   // h @ Wg
__device__ float g_es[NN];
__device__ float g_ed[NN];
__device__ int   g_deg[NN];
__device__ int   g_start[NN];                    // CSR range start (unordered alloc)
__device__ int   g_cur[NN];
__device__ int   g_total;                        // global CSR cursor
__device__ int   g_csrc[EE];                     // CSR by dst: source node ids
__device__ __align__(16) float g_pooled[NG * D_H];
__device__ int   g_is64;                         // runtime index-dtype flag

__device__ __forceinline__ float leaky(float x) {
    return x >= 0.f ? x : SLOPE * x;
}

// Load index i from a buffer that is either int32 or int64, per g_is64.
__device__ __forceinline__ int load_idx(const void* p, long long i) {
    return g_is64 ? (int)((const long long*)p)[i] : ((const int*)p)[i];
}

// ---------------------------------------------------------------------------
// Index dtype detection: for int64 node ids (< 50000) every odd 32-bit word
// is zero; for int32 they are random node ids (essentially never all zero).
// ---------------------------------------------------------------------------
__global__ void k_detect(const int* __restrict__ eiw) {
    if (threadIdx.x == 0 && blockIdx.x == 0) {
        int is64 = 1;
        #pragma unroll 1
        for (int i = 0; i < 64; i++) {
            if (eiw[2 * i + 1] != 0) { is64 = 0; break; }
        }
        g_is64 = is64;
    }
}

// ---------------------------------------------------------------------------
// CSR build (no prefix scan: ranges allocated with a global atomic cursor;
// range ORDER is irrelevant for correctness, only contiguity per dst)
// ---------------------------------------------------------------------------
__global__ void k_zero_deg() {
    int i = blockIdx.x * blockDim.x + threadIdx.x;
    if (i < NN) g_deg[i] = 0;
    if (i == 0) g_total = 0;
}

__global__ void k_hist(const void* __restrict__ ei) {
    int e = blockIdx.x * blockDim.x + threadIdx.x;
    if (e < EE) {
        int d = load_idx(ei, (long long)EE + e);
        if ((unsigned)d < NN) atomicAdd(&g_deg[d], 1);
    }
}

__global__ void k_alloc() {
    int i = blockIdx.x * blockDim.x + threadIdx.x;
    if (i < NN) {
        int dg = g_deg[i];
        int st = atomicAdd(&g_total, dg);   // warp-aggregated by ptxas
        g_start[i] = st;
        g_cur[i]   = st;
    }
}

__global__ void k_scatter(const void* __restrict__ ei) {
    int e = blockIdx.x * blockDim.x + threadIdx.x;
    if (e < EE) {
        int s = load_idx(ei, e);
        int d = load_idx(ei, (long long)EE + e);
        if ((unsigned)d < NN && (unsigned)s < NN) {
            int pos = atomicAdd(&g_cur[d], 1);
            g_csrc[pos] = s;
        }
    }
}

// ---------------------------------------------------------------------------
// SGEMM core: C[M,128] = A[M,128] @ B[128,128] (+bias)
// BM=64, BN=128, BK=16; 256 threads; thread tile 4x8
// ---------------------------------------------------------------------------
__device__ __forceinline__ void sgemm128_body(const float* __restrict__ A,
                                              const float* __restrict__ B,
                                              const float* __restrict__ bias,
                                              float* __restrict__ C, int M) {
    __shared__ __align__(16) float As[16][64];
    __shared__ __align__(16) float Bs[16][128];
    const int tid = threadIdx.x;
    const int brow = blockIdx.x * 64;
    const int tx = tid & 15;          // col group 0..15 -> cols tx*8..tx*8+7
    const int ty = tid >> 4;          // row group 0..15 -> rows ty*4..ty*4+3

    const int ar = tid >> 2;          // 0..63 row within tile
    const int ak = (tid & 3) * 4;     // 0,4,8,12 k chunk
    const int bk = tid >> 5;          // 0..7
    const int bc = (tid & 31) * 4;    // 0..124

    float acc[4][8];
    #pragma unroll
    for (int r = 0; r < 4; r++)
        #pragma unroll
        for (int c = 0; c < 8; c++) acc[r][c] = 0.f;

    for (int k0 = 0; k0 < 128; k0 += 16) {
        int grow = brow + ar;
        float4 av = (grow < M) ? *(const float4*)&A[(size_t)grow * 128 + k0 + ak]
                               : make_float4(0.f, 0.f, 0.f, 0.f);
        As[ak + 0][ar] = av.x;
        As[ak + 1][ar] = av.y;
        As[ak + 2][ar] = av.z;
        As[ak + 3][ar] = av.w;
        *(float4*)&Bs[bk][bc]     = *(const float4*)&B[(k0 + bk) * 128 + bc];
        *(float4*)&Bs[bk + 8][bc] = *(const float4*)&B[(k0 + bk + 8) * 128 + bc];
        __syncthreads();

        #pragma unroll
        for (int k = 0; k < 16; k++) {
            float4 a4 = *(const float4*)&As[k][ty * 4];
            float4 b0 = *(const float4*)&Bs[k][tx * 8];
            float4 b1 = *(const float4*)&Bs[k][tx * 8 + 4];
            float av_[4] = {a4.x, a4.y, a4.z, a4.w};
            float bv_[8] = {b0.x, b0.y, b0.z, b0.w, b1.x, b1.y, b1.z, b1.w};
            #pragma unroll
            for (int r = 0; r < 4; r++)
                #pragma unroll
                for (int c = 0; c < 8; c++)
                    acc[r][c] = fmaf(av_[r], bv_[c], acc[r][c]);
        }
        __syncthreads();
    }

    float bv[8];
    #pragma unroll
    for (int c = 0; c < 8; c++) bv[c] = bias ? bias[tx * 8 + c] : 0.f;

    #pragma unroll
    for (int r = 0; r < 4; r++) {
        int row = brow + ty * 4 + r;
        if (row < M) {
            float4 o0, o1;
            o0.x = acc[r][0] + bv[0]; o0.y = acc[r][1] + bv[1];
            o0.z = acc[r][2] + bv[2]; o0.w = acc[r][3] + bv[3];
            o1.x = acc[r][4] + bv[4]; o1.y = acc[r][5] + bv[5];
            o1.z = acc[r][6] + bv[6]; o1.w = acc[r][7] + bv[7];
            *(float4*)&C[(size_t)row * 128 + tx * 8]     = o0;
            *(float4*)&C[(size_t)row * 128 + tx * 8 + 4] = o1;
        }
    }
}

// mlp1: g_h = x @ W1 + b1
__global__ void k_sgemm_x(const float* __restrict__ A,
                          const float* __restrict__ B,
                          const float* __restrict__ bias) {
    sgemm128_body(A, B, bias, g_h, NN);
}

// per-layer: g_hp = g_h @ Wg[l]   (no bias)
__global__ void k_sgemm_h(const float* __restrict__ B) {
    sgemm128_body(g_h, B, nullptr, g_hp, NN);
}

// ---------------------------------------------------------------------------
// es/ed: per-node dot products hp . a_src, hp . a_dst  (warp per node)
// ---------------------------------------------------------------------------
__global__ void k_esed(const float* __restrict__ asrc,
                       const float* __restrict__ adst) {
    int warp = (blockIdx.x * blockDim.x + threadIdx.x) >> 5;
    int lane = threadIdx.x & 31;
    if (warp >= NN) return;
    const float4* hp4 = (const float4*)g_hp;
    float4 v = hp4[(size_t)warp * 32 + lane];
    float4 a = ((const float4*)asrc)[lane];
    float4 b = ((const float4*)adst)[lane];
    float ps = v.x * a.x + v.y * a.y + v.z * a.z + v.w * a.w;
    float pd = v.x * b.x + v.y * b.y + v.z * b.z + v.w * b.w;
    #pragma unroll
    for (int o = 16; o; o >>= 1) {
        ps += __shfl_xor_sync(0xffffffffu, ps, o);
        pd += __shfl_xor_sync(0xffffffffu, pd, o);
    }
    if (lane == 0) {
        g_es[warp] = ps;
        g_ed[warp] = pd;
    }
}

// ---------------------------------------------------------------------------
// GAT aggregation (warp per destination node): segment softmax + weighted
// gather + bias + relu + residual, all fused. Two edge passes:
//   pass 1 (strided): segment max
//   pass 2 (serial):  unnormalized weighted sum + z accumulation, then *invz
// ---------------------------------------------------------------------------
__global__ void k_gat_aggr(const float* __restrict__ bg) {
    int warp = (blockIdx.x * blockDim.x + threadIdx.x) >> 5;
    int lane = threadIdx.x & 31;
    if (warp >= NN) return;
    const int d = warp;
    const int lo = g_start[d], hi = lo + g_deg[d];
    const float es_d = g_es[d], ed_d = g_ed[d];
    const float e_self = leaky(es_d + ed_d);

    // pass 1: segment max (self-loop included)
    float m = e_self;
    for (int j = lo + lane; j < hi; j += 32) {
        int s = g_csrc[j];
        m = fmaxf(m, leaky(g_es[s] + ed_d));
    }
    #pragma unroll
    for (int o = 16; o; o >>= 1) m = fmaxf(m, __shfl_xor_sync(0xffffffffu, m, o));

    const float4* hp4 = (const float4*)g_hp;
    float4* h4 = (float4*)g_h;

    // pass 2: self-loop + serial edge loop, accumulate unnormalized sum and z
    float ex_self = expf(e_self - m);
    float z = ex_self;
    float4 v = hp4[(size_t)d * 32 + lane];
    float4 acc;
    acc.x = ex_self * v.x; acc.y = ex_self * v.y;
    acc.z = ex_self * v.z; acc.w = ex_self * v.w;

    for (int j = lo; j < hi; ++j) {
        int s = g_csrc[j];                                 // broadcast load
        float ex = expf(leaky(g_es[s] + ed_d) - m);        // identical across lanes
        z += ex;
        float4 w = hp4[(size_t)s * 32 + lane];
        acc.x = fmaf(ex, w.x, acc.x);
        acc.y = fmaf(ex, w.y, acc.y);
        acc.z = fmaf(ex, w.z, acc.z);
        acc.w = fmaf(ex, w.w, acc.w);
    }
    const float invz = 1.0f / z;

    // normalize + bias, relu, residual
    float4 b = ((const float4*)bg)[lane];
    float4 hin = h4[(size_t)d * 32 + lane];
    float4 o;
    o.x = fmaxf(fmaf(acc.x, invz, b.x), 0.f) + hin.x;
    o.y = fmaxf(fmaf(acc.y, invz, b.y), 0.f) + hin.y;
    o.z = fmaxf(fmaf(acc.z, invz, b.z), 0.f) + hin.z;
    o.w = fmaxf(fmaf(acc.w, invz, b.w), 0.f) + hin.w;
    h4[(size_t)d * 32 + lane] = o;
}

// ---------------------------------------------------------------------------
// Global add pool: batch is sorted; one block per graph, binary search range.
// ---------------------------------------------------------------------------
__global__ void k_pool(const void* __restrict__ batch) {
    __shared__ int s_lo, s_hi;
    const int g = blockIdx.x;
    const int tid = threadIdx.x; // 0..127 = feature column
    if (tid == 0) {
        int lo = 0, hi = NN;
        while (lo < hi) { int mid = (lo + hi) >> 1; if (load_idx(batch, mid) < g) lo = mid + 1; else hi = mid; }
        s_lo = lo;
        lo = 0; hi = NN;
        int g1 = g + 1;
        while (lo < hi) { int mid = (lo + hi) >> 1; if (load_idx(batch, mid) < g1) lo = mid + 1; else hi = mid; }
        s_hi = lo;
    }
    __syncthreads();
    float acc = 0.f;
    for (int i = s_lo; i < s_hi; ++i) acc += g_h[(size_t)i * 128 + tid];
    g_pooled[g * 128 + tid] = acc;
}

// out[g, o] = b2[o] + sum_k pooled[g,k] * W2[k,o]
__global__ void k_final(const float* __restrict__ W2,
                        const float* __restrict__ b2,
                        float* __restrict__ out) {
    const int g = blockIdx.x;   // 0..63
    const int o = threadIdx.x;  // 0..63
    float acc = b2[o];
    #pragma unroll 8
    for (int k = 0; k < 128; ++k)
        acc = fmaf(g_pooled[g * 128 + k], W2[k * 64 + o], acc);
    out[g * 64 + o] = acc;
}

// ---------------------------------------------------------------------------
// Launch (kernel launches only — fully graph-capturable)
// ---------------------------------------------------------------------------
extern "C" void kernel_launch(void* const* d_in, const int* in_sizes, int n_in,
                              void* d_out, int out_size) {
    const float* x     = (const float*)d_in[0];
    const void*  ei    = d_in[1];
    const void*  batch = d_in[2];
    const float* W1    = (const float*)d_in[3];
    const float* b1    = (const float*)d_in[4];
    const float* Wg    = (const float*)d_in[5];
    const float* asrc  = (const float*)d_in[6];
    const float* adst  = (const float*)d_in[7];
    const float* bg    = (const float*)d_in[8];
    const float* W2    = (const float*)d_in[9];
    const float* b2    = (const float*)d_in[10];
    float*       out   = (float*)d_out;

    // index dtype detection, then CSR build (scan-free)
    k_detect<<<1, 32>>>((const int*)ei);
    k_zero_deg<<<(NN + 255) / 256, 256>>>();
    k_hist<<<(EE + 255) / 256, 256>>>(ei);
    k_alloc<<<(NN + 255) / 256, 256>>>();
    k_scatter<<<(EE + 255) / 256, 256>>>(ei);

    const int gemm_blocks = (NN + 63) / 64;
    const int node_warp_blocks = (NN * 32 + 255) / 256;

    // mlp1: h = x @ W1 + b1
    k_sgemm_x<<<gemm_blocks, 256>>>(x, W1, b1);

    for (int l = 0; l < NLAYERS; ++l) {
        k_sgemm_h<<<gemm_blocks, 256>>>(Wg + (size_t)l * 128 * 128);
        k_esed<<<node_warp_blocks, 256>>>(asrc + l * 128, adst + l * 128);
        k_gat_aggr<<<node_warp_blocks, 256>>>(bg + l * 128);
    }

    k_pool<<<NG, 128>>>(batch);
    k_final<<<NG, 64>>>(W2, b2, out);
}

// round 5
// speedup vs baseline: 1.4274x; 1.2641x over previous
#include <cuda_runtime.h>
#include <cuda_bf16.h>
#include <math.h>
#include <stdint.h>

// Problem constants (match reference)
#define NN      50000
#define EE      600000
#define D_IN    128
#define D_H     128
#define D_OUT   64
#define NLAYERS 3
#define NG      64
#define SLOPE   0.2f

// ---------------------------------------------------------------------------
// Device scratch
// ---------------------------------------------------------------------------
__device__ __align__(16) float g_h [NN * D_H];
__device__ __align__(16) float g_hp[NN * D_H];
__device__ float g_es[NN];
__device__ float g_ed[NN];
__device__ int   g_deg[NN];
__device__ int   g_start[NN];
__device__ int   g_cur[NN];
__device__ int   g_total;
__device__ int   g_csrc[EE];
__device__ __align__(16) float g_pooled[NG * D_H];
__device__ int   g_is64;

__device__ __forceinline__ float leaky(float x) {
    return x >= 0.f ? x : SLOPE * x;
}

__device__ __forceinline__ int load_idx(const void* p, long long i) {
    return g_is64 ? (int)((const long long*)p)[i] : ((const int*)p)[i];
}

__device__ __forceinline__ uint32_t f2tf32(float x) {
    uint32_t r;
    asm("cvt.rna.tf32.f32 %0, %1;" : "=r"(r) : "f"(x));
    return r;
}

__device__ __forceinline__ void mma_tf32(float c[4], const uint32_t a[4],
                                         uint32_t b0, uint32_t b1) {
    asm volatile(
        "mma.sync.aligned.m16n8k8.row.col.f32.tf32.tf32.f32 "
        "{%0,%1,%2,%3}, {%4,%5,%6,%7}, {%8,%9}, {%0,%1,%2,%3};\n"
        : "+f"(c[0]), "+f"(c[1]), "+f"(c[2]), "+f"(c[3])
        : "r"(a[0]), "r"(a[1]), "r"(a[2]), "r"(a[3]), "r"(b0), "r"(b1));
}

// ---------------------------------------------------------------------------
// Index dtype detection
// ---------------------------------------------------------------------------
__global__ void k_detect(const int* __restrict__ eiw) {
    if (threadIdx.x == 0 && blockIdx.x == 0) {
        int is64 = 1;
        #pragma unroll 1
        for (int i = 0; i < 64; i++) {
            if (eiw[2 * i + 1] != 0) { is64 = 0; break; }
        }
        g_is64 = is64;
    }
}

// ---------------------------------------------------------------------------
// CSR build (scan-free; per-dst ranges via global atomic cursor)
// ---------------------------------------------------------------------------
__global__ void k_zero_deg() {
    int i = blockIdx.x * blockDim.x + threadIdx.x;
    if (i < NN) g_deg[i] = 0;
    if (i == 0) g_total = 0;
}

__global__ void k_hist(const void* __restrict__ ei) {
    int e = blockIdx.x * blockDim.x + threadIdx.x;
    if (e < EE) {
        int d = load_idx(ei, (long long)EE + e);
        if ((unsigned)d < NN) atomicAdd(&g_deg[d], 1);
    }
}

__global__ void k_alloc() {
    int i = blockIdx.x * blockDim.x + threadIdx.x;
    if (i < NN) {
        int dg = g_deg[i];
        int st = atomicAdd(&g_total, dg);
        g_start[i] = st;
        g_cur[i]   = st;
    }
}

__global__ void k_scatter(const void* __restrict__ ei) {
    int e = blockIdx.x * blockDim.x + threadIdx.x;
    if (e < EE) {
        int s = load_idx(ei, e);
        int d = load_idx(ei, (long long)EE + e);
        if ((unsigned)d < NN && (unsigned)s < NN) {
            int pos = atomicAdd(&g_cur[d], 1);
            g_csrc[pos] = s;
        }
    }
}

// ---------------------------------------------------------------------------
// 3xTF32 tensor-core GEMM: C[M,128] = A[M,128] @ B[128,128] (+bias)
// Block 128x128, 256 threads (8 warps, 2x4), warp tile 64x32, BK=16.
// A,B split into tf32 hi/lo in smem; acc += Ah*Bh + Ah*Bl + Al*Bh (fp32 acc).
// ---------------------------------------------------------------------------
#define PAD 136   // smem row stride (uint32): 136 % 32 == 8 -> conflict-free frags

__device__ __forceinline__ void mma_gemm_body(const float* __restrict__ A,
                                              const float* __restrict__ B,
                                              const float* __restrict__ bias,
                                              float* __restrict__ C, int M) {
    __shared__ uint32_t Ah[16][PAD], Al[16][PAD];
    __shared__ uint32_t Bh[16][PAD], Bl[16][PAD];

    const int tid  = threadIdx.x;
    const int warp = tid >> 5, lane = tid & 31;
    const int wm = warp >> 2, wn = warp & 3;   // 2 x 4 warp grid
    const int gid = lane >> 2, tig = lane & 3;
    const int brow = blockIdx.x * 128;

    // A loader: row = (tid&63) + 64*p, k-quad = (tid>>6)*4
    const int a_r  = tid & 63;
    const int a_lk = (tid >> 6) * 4;
    // B loader: k-row = tid>>4 (0..15), col base = (tid&15)*8
    const int b_k  = tid >> 4;
    const int b_n  = (tid & 15) * 8;

    float acc[4][4][4];
    #pragma unroll
    for (int mt = 0; mt < 4; mt++)
        #pragma unroll
        for (int nt = 0; nt < 4; nt++)
            #pragma unroll
            for (int c = 0; c < 4; c++) acc[mt][nt][c] = 0.f;

    for (int kc = 0; kc < 128; kc += 16) {
        // ---- stage A (with tf32 hi/lo split), transposed to [k][m]
        #pragma unroll
        for (int p = 0; p < 2; p++) {
            int r = a_r + 64 * p;
            int grow = brow + r;
            float4 v = (grow < M) ? *(const float4*)&A[(size_t)grow * 128 + kc + a_lk]
                                  : make_float4(0.f, 0.f, 0.f, 0.f);
            float f[4] = {v.x, v.y, v.z, v.w};
            #pragma unroll
            for (int i = 0; i < 4; i++) {
                uint32_t h = f2tf32(f[i]);
                float lo = f[i] - __uint_as_float(h);
                Ah[a_lk + i][r] = h;
                Al[a_lk + i][r] = f2tf32(lo);
            }
        }
        // ---- stage B: [k][n]
        #pragma unroll
        for (int p = 0; p < 2; p++) {
            float4 v = *(const float4*)&B[(kc + b_k) * 128 + b_n + 4 * p];
            float f[4] = {v.x, v.y, v.z, v.w};
            uint4 hq, lq;
            uint32_t* hp_ = (uint32_t*)&hq;
            uint32_t* lp_ = (uint32_t*)&lq;
            #pragma unroll
            for (int i = 0; i < 4; i++) {
                uint32_t h = f2tf32(f[i]);
                float lo = f[i] - __uint_as_float(h);
                hp_[i] = h;
                lp_[i] = f2tf32(lo);
            }
            *(uint4*)&Bh[b_k][b_n + 4 * p] = hq;
            *(uint4*)&Bl[b_k][b_n + 4 * p] = lq;
        }
        __syncthreads();

        #pragma unroll
        for (int ks = 0; ks < 16; ks += 8) {
            const int k0 = ks + tig;
            // A fragments (hi & lo) for 4 m-tiles
            uint32_t ah[4][4], al[4][4];
            #pragma unroll
            for (int mt = 0; mt < 4; mt++) {
                int m0 = wm * 64 + mt * 16 + gid;
                ah[mt][0] = Ah[k0][m0];     ah[mt][1] = Ah[k0][m0 + 8];
                ah[mt][2] = Ah[k0 + 4][m0]; ah[mt][3] = Ah[k0 + 4][m0 + 8];
                al[mt][0] = Al[k0][m0];     al[mt][1] = Al[k0][m0 + 8];
                al[mt][2] = Al[k0 + 4][m0]; al[mt][3] = Al[k0 + 4][m0 + 8];
            }
            #pragma unroll
            for (int nt = 0; nt < 4; nt++) {
                int n0 = wn * 32 + nt * 8 + gid;
                uint32_t bh0 = Bh[k0][n0], bh1 = Bh[k0 + 4][n0];
                uint32_t bl0 = Bl[k0][n0], bl1 = Bl[k0 + 4][n0];
                #pragma unroll
                for (int mt = 0; mt < 4; mt++) {
                    mma_tf32(acc[mt][nt], ah[mt], bh0, bh1);  // hi*hi
                    mma_tf32(acc[mt][nt], ah[mt], bl0, bl1);  // hi*lo
                    mma_tf32(acc[mt][nt], al[mt], bh0, bh1);  // lo*hi
                }
            }
        }
        __syncthreads();
    }

    // epilogue
    #pragma unroll
    for (int mt = 0; mt < 4; mt++) {
        int r0 = brow + wm * 64 + mt * 16 + gid;
        #pragma unroll
        for (int nt = 0; nt < 4; nt++) {
            int c0 = wn * 32 + nt * 8 + 2 * tig;
            float b0v = bias ? bias[c0]     : 0.f;
            float b1v = bias ? bias[c0 + 1] : 0.f;
            if (r0 < M) {
                float2 v = make_float2(acc[mt][nt][0] + b0v, acc[mt][nt][1] + b1v);
                *(float2*)&C[(size_t)r0 * 128 + c0] = v;
            }
            if (r0 + 8 < M) {
                float2 v = make_float2(acc[mt][nt][2] + b0v, acc[mt][nt][3] + b1v);
                *(float2*)&C[(size_t)(r0 + 8) * 128 + c0] = v;
            }
        }
    }
}

__global__ void __launch_bounds__(256) k_mma_x(const float* __restrict__ A,
                                               const float* __restrict__ B,
                                               const float* __restrict__ bias) {
    mma_gemm_body(A, B, bias, g_h, NN);
}

__global__ void __launch_bounds__(256) k_mma_h(const float* __restrict__ B) {
    mma_gemm_body(g_h, B, nullptr, g_hp, NN);
}

// ---------------------------------------------------------------------------
// es/ed: per-node dot products hp . a_src, hp . a_dst  (warp per node)
// ---------------------------------------------------------------------------
__global__ void k_esed(const float* __restrict__ asrc,
                       const float* __restrict__ adst) {
    int warp = (blockIdx.x * blockDim.x + threadIdx.x) >> 5;
    int lane = threadIdx.x & 31;
    if (warp >= NN) return;
    const float4* hp4 = (const float4*)g_hp;
    float4 v = hp4[(size_t)warp * 32 + lane];
    float4 a = ((const float4*)asrc)[lane];
    float4 b = ((const float4*)adst)[lane];
    float ps = v.x * a.x + v.y * a.y + v.z * a.z + v.w * a.w;
    float pd = v.x * b.x + v.y * b.y + v.z * b.z + v.w * b.w;
    #pragma unroll
    for (int o = 16; o; o >>= 1) {
        ps += __shfl_xor_sync(0xffffffffu, ps, o);
        pd += __shfl_xor_sync(0xffffffffu, pd, o);
    }
    if (lane == 0) {
        g_es[warp] = ps;
        g_ed[warp] = pd;
    }
}

// ---------------------------------------------------------------------------
// GAT aggregation (warp per destination node)
// ---------------------------------------------------------------------------
__global__ void k_gat_aggr(const float* __restrict__ bg) {
    int warp = (blockIdx.x * blockDim.x + threadIdx.x) >> 5;
    int lane = threadIdx.x & 31;
    if (warp >= NN) return;
    const int d = warp;
    const int lo = g_start[d], hi = lo + g_deg[d];
    const float es_d = g_es[d], ed_d = g_ed[d];
    const float e_self = leaky(es_d + ed_d);

    // pass 1: segment max
    float m = e_self;
    for (int j = lo + lane; j < hi; j += 32) {
        int s = g_csrc[j];
        m = fmaxf(m, leaky(g_es[s] + ed_d));
    }
    #pragma unroll
    for (int o = 16; o; o >>= 1) m = fmaxf(m, __shfl_xor_sync(0xffffffffu, m, o));

    const float4* hp4 = (const float4*)g_hp;
    float4* h4 = (float4*)g_h;

    // pass 2: unnormalized weighted sum + z
    float ex_self = expf(e_self - m);
    float z = ex_self;
    float4 v = hp4[(size_t)d * 32 + lane];
    float4 acc;
    acc.x = ex_self * v.x; acc.y = ex_self * v.y;
    acc.z = ex_self * v.z; acc.w = ex_self * v.w;

    for (int j = lo; j < hi; ++j) {
        int s = g_csrc[j];
        float ex = expf(leaky(g_es[s] + ed_d) - m);
        z += ex;
        float4 w = hp4[(size_t)s * 32 + lane];
        acc.x = fmaf(ex, w.x, acc.x);
        acc.y = fmaf(ex, w.y, acc.y);
        acc.z = fmaf(ex, w.z, acc.z);
        acc.w = fmaf(ex, w.w, acc.w);
    }
    const float invz = 1.0f / z;

    float4 b = ((const float4*)bg)[lane];
    float4 hin = h4[(size_t)d * 32 + lane];
    float4 o;
    o.x = fmaxf(fmaf(acc.x, invz, b.x), 0.f) + hin.x;
    o.y = fmaxf(fmaf(acc.y, invz, b.y), 0.f) + hin.y;
    o.z = fmaxf(fmaf(acc.z, invz, b.z), 0.f) + hin.z;
    o.w = fmaxf(fmaf(acc.w, invz, b.w), 0.f) + hin.w;
    h4[(size_t)d * 32 + lane] = o;
}

// ---------------------------------------------------------------------------
// Global add pool + final projection
// ---------------------------------------------------------------------------
__global__ void k_pool(const void* __restrict__ batch) {
    __shared__ int s_lo, s_hi;
    const int g = blockIdx.x;
    const int tid = threadIdx.x;
    if (tid == 0) {
        int lo = 0, hi = NN;
        while (lo < hi) { int mid = (lo + hi) >> 1; if (load_idx(batch, mid) < g) lo = mid + 1; else hi = mid; }
        s_lo = lo;
        lo = 0; hi = NN;
        int g1 = g + 1;
        while (lo < hi) { int mid = (lo + hi) >> 1; if (load_idx(batch, mid) < g1) lo = mid + 1; else hi = mid; }
        s_hi = lo;
    }
    __syncthreads();
    float acc = 0.f;
    for (int i = s_lo; i < s_hi; ++i) acc += g_h[(size_t)i * 128 + tid];
    g_pooled[g * 128 + tid] = acc;
}

__global__ void k_final(const float* __restrict__ W2,
                        const float* __restrict__ b2,
                        float* __restrict__ out) {
    const int g = blockIdx.x;
    const int o = threadIdx.x;
    float acc = b2[o];
    #pragma unroll 8
    for (int k = 0; k < 128; ++k)
        acc = fmaf(g_pooled[g * 128 + k], W2[k * 64 + o], acc);
    out[g * 64 + o] = acc;
}

// ---------------------------------------------------------------------------
// Launch
// ---------------------------------------------------------------------------
extern "C" void kernel_launch(void* const* d_in, const int* in_sizes, int n_in,
                              void* d_out, int out_size) {
    const float* x     = (const float*)d_in[0];
    const void*  ei    = d_in[1];
    const void*  batch = d_in[2];
    const float* W1    = (const float*)d_in[3];
    const float* b1    = (const float*)d_in[4];
    const float* Wg    = (const float*)d_in[5];
    const float* asrc  = (const float*)d_in[6];
    const float* adst  = (const float*)d_in[7];
    const float* bg    = (const float*)d_in[8];
    const float* W2    = (const float*)d_in[9];
    const float* b2    = (const float*)d_in[10];
    float*       out   = (float*)d_out;

    k_detect<<<1, 32>>>((const int*)ei);
    k_zero_deg<<<(NN + 255) / 256, 256>>>();
    k_hist<<<(EE + 255) / 256, 256>>>(ei);
    k_alloc<<<(NN + 255) / 256, 256>>>();
    k_scatter<<<(EE + 255) / 256, 256>>>(ei);

    const int gemm_blocks = (NN + 127) / 128;
    const int node_warp_blocks = (NN * 32 + 255) / 256;

    k_mma_x<<<gemm_blocks, 256>>>(x, W1, b1);

    for (int l = 0; l < NLAYERS; ++l) {
        k_mma_h<<<gemm_blocks, 256>>>(Wg + (size_t)l * 128 * 128);
        k_esed<<<node_warp_blocks, 256>>>(asrc + l * 128, adst + l * 128);
        k_gat_aggr<<<node_warp_blocks, 256>>>(bg + l * 128);
    }

    k_pool<<<NG, 128>>>(batch);
    k_final<<<NG, 64>>>(W2, b2, out);
}

// round 6
// speedup vs baseline: 1.5227x; 1.0667x over previous
#include <cuda_runtime.h>
#include <cuda_bf16.h>
#include <math.h>
#include <stdint.h>

// Problem constants (match reference)
#define NN      50000
#define EE      600000
#define D_IN    128
#define D_H     128
#define D_OUT   64
#define NLAYERS 3
#define NG      64
#define SLOPE   0.2f
#define POOL_SL 8

// ---------------------------------------------------------------------------
// Device scratch
// ---------------------------------------------------------------------------
__device__ __align__(16) float g_h [NN * D_H];
__device__ __align__(16) float g_hp[NN * D_H];
__device__ float g_es[NN];
__device__ float g_ed[NN];
__device__ float g_ee[EE];                      // cached per-edge leaky scores
__device__ int   g_deg[NN];
__device__ int   g_start[NN];
__device__ int   g_cur[NN];
__device__ int   g_total;
__device__ int   g_csrc[EE];
__device__ __align__(16) float g_pooled[NG * D_H];
__device__ int   g_is64;

__device__ __forceinline__ float leaky(float x) {
    return x >= 0.f ? x : SLOPE * x;
}

__device__ __forceinline__ int load_idx(const void* p, long long i) {
    return g_is64 ? (int)((const long long*)p)[i] : ((const int*)p)[i];
}

__device__ __forceinline__ uint32_t f2tf32(float x) {
    uint32_t r;
    asm("cvt.rna.tf32.f32 %0, %1;" : "=r"(r) : "f"(x));
    return r;
}

__device__ __forceinline__ void mma_tf32(float c[4], const uint32_t a[4],
                                         uint32_t b0, uint32_t b1) {
    asm volatile(
        "mma.sync.aligned.m16n8k8.row.col.f32.tf32.tf32.f32 "
        "{%0,%1,%2,%3}, {%4,%5,%6,%7}, {%8,%9}, {%0,%1,%2,%3};\n"
        : "+f"(c[0]), "+f"(c[1]), "+f"(c[2]), "+f"(c[3])
        : "r"(a[0]), "r"(a[1]), "r"(a[2]), "r"(a[3]), "r"(b0), "r"(b1));
}

// ---------------------------------------------------------------------------
// init: zero degrees + pooled accumulator + cursor, detect index dtype
// ---------------------------------------------------------------------------
__global__ void k_init(const int* __restrict__ eiw) {
    int i = blockIdx.x * blockDim.x + threadIdx.x;
    if (i < NN) g_deg[i] = 0;
    if (i < NG * D_H) g_pooled[i] = 0.f;
    if (i == 0) {
        g_total = 0;
        int is64 = 1;
        #pragma unroll 1
        for (int t = 0; t < 64; t++) {
            if (eiw[2 * t + 1] != 0) { is64 = 0; break; }
        }
        g_is64 = is64;
    }
}

// ---------------------------------------------------------------------------
// CSR build (scan-free; per-dst ranges via global atomic cursor)
// ---------------------------------------------------------------------------
__global__ void k_hist(const void* __restrict__ ei) {
    int e = blockIdx.x * blockDim.x + threadIdx.x;
    if (e < EE) {
        int d = load_idx(ei, (long long)EE + e);
        if ((unsigned)d < NN) atomicAdd(&g_deg[d], 1);
    }
}

__global__ void k_alloc() {
    int i = blockIdx.x * blockDim.x + threadIdx.x;
    if (i < NN) {
        int dg = g_deg[i];
        int st = atomicAdd(&g_total, dg);
        g_start[i] = st;
        g_cur[i]   = st;
    }
}

__global__ void k_scatter(const void* __restrict__ ei) {
    int e = blockIdx.x * blockDim.x + threadIdx.x;
    if (e < EE) {
        int s = load_idx(ei, e);
        int d = load_idx(ei, (long long)EE + e);
        if ((unsigned)d < NN && (unsigned)s < NN) {
            int pos = atomicAdd(&g_cur[d], 1);
            g_csrc[pos] = s;
        }
    }
}

// ---------------------------------------------------------------------------
// 3xTF32 tensor-core GEMM: C[M,128] = A[M,128] @ B[128,128] (+bias)
// Block 128x128, 256 threads (8 warps, 2x4), warp tile 64x32, BK=16.
// Optional fused epilogue: es/ed row-dots with asrc/adst (FUSE_ESED).
// ---------------------------------------------------------------------------
#define PAD 136   // smem row stride (uint32): conflict-free fragment loads

template <bool FUSE_ESED>
__device__ __forceinline__ void mma_gemm_body(const float* __restrict__ A,
                                              const float* __restrict__ B,
                                              const float* __restrict__ bias,
                                              const float* __restrict__ asrc,
                                              const float* __restrict__ adst,
                                              float* __restrict__ C, int M) {
    __shared__ uint32_t Ah[16][PAD], Al[16][PAD];
    __shared__ uint32_t Bh[16][PAD], Bl[16][PAD];
    __shared__ float es_s[128], ed_s[128];

    const int tid  = threadIdx.x;
    const int warp = tid >> 5, lane = tid & 31;
    const int wm = warp >> 2, wn = warp & 3;   // 2 x 4 warp grid
    const int gid = lane >> 2, tig = lane & 3;
    const int brow = blockIdx.x * 128;

    if (FUSE_ESED && tid < 128) { es_s[tid] = 0.f; ed_s[tid] = 0.f; }

    const int a_r  = tid & 63;
    const int a_lk = (tid >> 6) * 4;
    const int b_k  = tid >> 4;
    const int b_n  = (tid & 15) * 8;

    float acc[4][4][4];
    #pragma unroll
    for (int mt = 0; mt < 4; mt++)
        #pragma unroll
        for (int nt = 0; nt < 4; nt++)
            #pragma unroll
            for (int c = 0; c < 4; c++) acc[mt][nt][c] = 0.f;

    for (int kc = 0; kc < 128; kc += 16) {
        // ---- stage A (tf32 hi/lo split), transposed to [k][m]
        #pragma unroll
        for (int p = 0; p < 2; p++) {
            int r = a_r + 64 * p;
            int grow = brow + r;
            float4 v = (grow < M) ? *(const float4*)&A[(size_t)grow * 128 + kc + a_lk]
                                  : make_float4(0.f, 0.f, 0.f, 0.f);
            float f[4] = {v.x, v.y, v.z, v.w};
            #pragma unroll
            for (int i = 0; i < 4; i++) {
                uint32_t h = f2tf32(f[i]);
                float lo = f[i] - __uint_as_float(h);
                Ah[a_lk + i][r] = h;
                Al[a_lk + i][r] = f2tf32(lo);
            }
        }
        // ---- stage B: [k][n]
        #pragma unroll
        for (int p = 0; p < 2; p++) {
            float4 v = *(const float4*)&B[(kc + b_k) * 128 + b_n + 4 * p];
            float f[4] = {v.x, v.y, v.z, v.w};
            uint4 hq, lq;
            uint32_t* hp_ = (uint32_t*)&hq;
            uint32_t* lp_ = (uint32_t*)&lq;
            #pragma unroll
            for (int i = 0; i < 4; i++) {
                uint32_t h = f2tf32(f[i]);
                float lo = f[i] - __uint_as_float(h);
                hp_[i] = h;
                lp_[i] = f2tf32(lo);
            }
            *(uint4*)&Bh[b_k][b_n + 4 * p] = hq;
            *(uint4*)&Bl[b_k][b_n + 4 * p] = lq;
        }
        __syncthreads();

        #pragma unroll
        for (int ks = 0; ks < 16; ks += 8) {
            const int k0 = ks + tig;
            uint32_t ah[4][4], al[4][4];
            #pragma unroll
            for (int mt = 0; mt < 4; mt++) {
                int m0 = wm * 64 + mt * 16 + gid;
                ah[mt][0] = Ah[k0][m0];     ah[mt][1] = Ah[k0][m0 + 8];
                ah[mt][2] = Ah[k0 + 4][m0]; ah[mt][3] = Ah[k0 + 4][m0 + 8];
                al[mt][0] = Al[k0][m0];     al[mt][1] = Al[k0][m0 + 8];
                al[mt][2] = Al[k0 + 4][m0]; al[mt][3] = Al[k0 + 4][m0 + 8];
            }
            #pragma unroll
            for (int nt = 0; nt < 4; nt++) {
                int n0 = wn * 32 + nt * 8 + gid;
                uint32_t bh0 = Bh[k0][n0], bh1 = Bh[k0 + 4][n0];
                uint32_t bl0 = Bl[k0][n0], bl1 = Bl[k0 + 4][n0];
                #pragma unroll
                for (int mt = 0; mt < 4; mt++) {
                    mma_tf32(acc[mt][nt], ah[mt], bh0, bh1);
                    mma_tf32(acc[mt][nt], ah[mt], bl0, bl1);
                    mma_tf32(acc[mt][nt], al[mt], bh0, bh1);
                }
            }
        }
        __syncthreads();
    }

    // attention-vector values for this thread's columns
    float as_v[4][2], ad_v[4][2];
    if (FUSE_ESED) {
        #pragma unroll
        for (int nt = 0; nt < 4; nt++) {
            int c0 = wn * 32 + nt * 8 + 2 * tig;
            as_v[nt][0] = asrc[c0]; as_v[nt][1] = asrc[c0 + 1];
            ad_v[nt][0] = adst[c0]; ad_v[nt][1] = adst[c0 + 1];
        }
    }

    // epilogue: store C (+bias) and accumulate es/ed partials
    #pragma unroll
    for (int mt = 0; mt < 4; mt++) {
        int r0 = brow + wm * 64 + mt * 16 + gid;
        float pe0 = 0.f, pe1 = 0.f, pd0 = 0.f, pd1 = 0.f;
        #pragma unroll
        for (int nt = 0; nt < 4; nt++) {
            int c0 = wn * 32 + nt * 8 + 2 * tig;
            float b0v = bias ? bias[c0]     : 0.f;
            float b1v = bias ? bias[c0 + 1] : 0.f;
            float v00 = acc[mt][nt][0] + b0v, v01 = acc[mt][nt][1] + b1v;
            float v10 = acc[mt][nt][2] + b0v, v11 = acc[mt][nt][3] + b1v;
            if (r0 < M)     *(float2*)&C[(size_t)r0 * 128 + c0]       = make_float2(v00, v01);
            if (r0 + 8 < M) *(float2*)&C[(size_t)(r0 + 8) * 128 + c0] = make_float2(v10, v11);
            if (FUSE_ESED) {
                pe0 += v00 * as_v[nt][0] + v01 * as_v[nt][1];
                pe1 += v10 * as_v[nt][0] + v11 * as_v[nt][1];
                pd0 += v00 * ad_v[nt][0] + v01 * ad_v[nt][1];
                pd1 += v10 * ad_v[nt][0] + v11 * ad_v[nt][1];
            }
        }
        if (FUSE_ESED) {
            #pragma unroll
            for (int o = 1; o <= 2; o <<= 1) {
                pe0 += __shfl_xor_sync(0xffffffffu, pe0, o);
                pe1 += __shfl_xor_sync(0xffffffffu, pe1, o);
                pd0 += __shfl_xor_sync(0xffffffffu, pd0, o);
                pd1 += __shfl_xor_sync(0xffffffffu, pd1, o);
            }
            if (tig == 0) {
                int lr = wm * 64 + mt * 16 + gid;
                atomicAdd(&es_s[lr], pe0);     atomicAdd(&es_s[lr + 8], pe1);
                atomicAdd(&ed_s[lr], pd0);     atomicAdd(&ed_s[lr + 8], pd1);
            }
        }
    }

    if (FUSE_ESED) {
        __syncthreads();
        if (tid < 128 && brow + tid < M) {
            g_es[brow + tid] = es_s[tid];
            g_ed[brow + tid] = ed_s[tid];
        }
    }
}

__global__ void __launch_bounds__(256) k_mma_x(const float* __restrict__ A,
                                               const float* __restrict__ B,
                                               const float* __restrict__ bias) {
    mma_gemm_body<false>(A, B, bias, nullptr, nullptr, g_h, NN);
}

__global__ void __launch_bounds__(256) k_mma_h(const float* __restrict__ B,
                                               const float* __restrict__ asrc,
                                               const float* __restrict__ adst) {
    mma_gemm_body<true>(g_h, B, nullptr, asrc, adst, g_hp, NN);
}

// ---------------------------------------------------------------------------
// GAT aggregation (warp per destination node)
//   pass 1 (strided): compute + cache per-edge scores, segment max
//   pass 2 (serial):  weighted feature sum + z, then normalize/bias/relu/res
// ---------------------------------------------------------------------------
__global__ void k_gat_aggr(const float* __restrict__ bg) {
    int warp = (blockIdx.x * blockDim.x + threadIdx.x) >> 5;
    int lane = threadIdx.x & 31;
    if (warp >= NN) return;
    const int d = warp;
    const int lo = g_start[d], hi = lo + g_deg[d];
    const float es_d = g_es[d], ed_d = g_ed[d];
    const float e_self = leaky(es_d + ed_d);

    // pass 1: edge scores + segment max
    float m = e_self;
    for (int j = lo + lane; j < hi; j += 32) {
        int s = g_csrc[j];
        float e = leaky(g_es[s] + ed_d);
        g_ee[j] = e;
        m = fmaxf(m, e);
    }
    #pragma unroll
    for (int o = 16; o; o >>= 1) m = fmaxf(m, __shfl_xor_sync(0xffffffffu, m, o));

    const float4* hp4 = (const float4*)g_hp;
    float4* h4 = (float4*)g_h;

    // pass 2: unnormalized weighted sum + z
    float ex_self = expf(e_self - m);
    float z = ex_self;
    float4 v = hp4[(size_t)d * 32 + lane];
    float4 acc;
    acc.x = ex_self * v.x; acc.y = ex_self * v.y;
    acc.z = ex_self * v.z; acc.w = ex_self * v.w;

    for (int j = lo; j < hi; ++j) {
        int s = g_csrc[j];
        float ex = expf(g_ee[j] - m);
        z += ex;
        float4 w = hp4[(size_t)s * 32 + lane];
        acc.x = fmaf(ex, w.x, acc.x);
        acc.y = fmaf(ex, w.y, acc.y);
        acc.z = fmaf(ex, w.z, acc.z);
        acc.w = fmaf(ex, w.w, acc.w);
    }
    const float invz = 1.0f / z;

    float4 b = ((const float4*)bg)[lane];
    float4 hin = h4[(size_t)d * 32 + lane];
    float4 o;
    o.x = fmaxf(fmaf(acc.x, invz, b.x), 0.f) + hin.x;
    o.y = fmaxf(fmaf(acc.y, invz, b.y), 0.f) + hin.y;
    o.z = fmaxf(fmaf(acc.z, invz, b.z), 0.f) + hin.z;
    o.w = fmaxf(fmaf(acc.w, invz, b.w), 0.f) + hin.w;
    h4[(size_t)d * 32 + lane] = o;
}

// ---------------------------------------------------------------------------
// Global add pool: grid (NG, POOL_SL); row-sliced, fp32 atomics into g_pooled
// ---------------------------------------------------------------------------
__global__ void k_pool(const void* __restrict__ batch) {
    __shared__ int s_lo, s_hi;
    const int g = blockIdx.x;
    const int tid = threadIdx.x;
    if (tid == 0) {
        int lo = 0, hi = NN;
        while (lo < hi) { int mid = (lo + hi) >> 1; if (load_idx(batch, mid) < g) lo = mid + 1; else hi = mid; }
        s_lo = lo;
        lo = 0; hi = NN;
        int g1 = g + 1;
        while (lo < hi) { int mid = (lo + hi) >> 1; if (load_idx(batch, mid) < g1) lo = mid + 1; else hi = mid; }
        s_hi = lo;
    }
    __syncthreads();
    float acc = 0.f;
    for (int i = s_lo + blockIdx.y; i < s_hi; i += POOL_SL)
        acc += g_h[(size_t)i * 128 + tid];
    atomicAdd(&g_pooled[g * 128 + tid], acc);
}

__global__ void k_final(const float* __restrict__ W2,
                        const float* __restrict__ b2,
                        float* __restrict__ out) {
    const int g = blockIdx.x;
    const int o = threadIdx.x;
    float acc = b2[o];
    #pragma unroll 8
    for (int k = 0; k < 128; ++k)
        acc = fmaf(g_pooled[g * 128 + k], W2[k * 64 + o], acc);
    out[g * 64 + o] = acc;
}

// ---------------------------------------------------------------------------
// Launch
// ---------------------------------------------------------------------------
extern "C" void kernel_launch(void* const* d_in, const int* in_sizes, int n_in,
                              void* d_out, int out_size) {
    const float* x     = (const float*)d_in[0];
    const void*  ei    = d_in[1];
    const void*  batch = d_in[2];
    const float* W1    = (const float*)d_in[3];
    const float* b1    = (const float*)d_in[4];
    const float* Wg    = (const float*)d_in[5];
    const float* asrc  = (const float*)d_in[6];
    const float* adst  = (const float*)d_in[7];
    const float* bg    = (const float*)d_in[8];
    const float* W2    = (const float*)d_in[9];
    const float* b2    = (const float*)d_in[10];
    float*       out   = (float*)d_out;

    k_init<<<(NN + 255) / 256, 256>>>((const int*)ei);
    k_hist<<<(EE + 255) / 256, 256>>>(ei);
    k_alloc<<<(NN + 255) / 256, 256>>>();
    k_scatter<<<(EE + 255) / 256, 256>>>(ei);

    const int gemm_blocks = (NN + 127) / 128;
    const int node_warp_blocks = (NN * 32 + 255) / 256;

    k_mma_x<<<gemm_blocks, 256>>>(x, W1, b1);

    for (int l = 0; l < NLAYERS; ++l) {
        k_mma_h<<<gemm_blocks, 256>>>(Wg + (size_t)l * 128 * 128,
                                      asrc + l * 128, adst + l * 128);
        k_gat_aggr<<<node_warp_blocks, 256>>>(bg + l * 128);
    }

    dim3 pool_grid(NG, POOL_SL);
    k_pool<<<pool_grid, 128>>>(batch);
    k_final<<<NG, 64>>>(W2, b2, out);
}

// round 7
// speedup vs baseline: 1.8654x; 1.2251x over previous
#include <cuda_runtime.h>
#include <cuda_bf16.h>
#include <math.h>
#include <stdint.h>

// Problem constants (match reference)
#define NN      50000
#define EE      600000
#define D_IN    128
#define D_H     128
#define D_OUT   64
#define NLAYERS 3
#define NG      64
#define SLOPE   0.2f

// ---------------------------------------------------------------------------
// Device scratch
// ---------------------------------------------------------------------------
__device__ __align__(16) float g_h [NN * D_H];
__device__ __align__(16) float g_hp[NN * D_H];
__device__ float g_es[NN];
__device__ float g_ed[NN];
__device__ float g_ee[EE];                      // cached per-edge leaky scores
__device__ int   g_deg[NN];
__device__ int   g_start[NN];
__device__ int   g_cur[NN];
__device__ int   g_total;
__device__ int   g_csrc[EE];
__device__ int   g_is64;

__device__ __forceinline__ float leaky(float x) {
    return x >= 0.f ? x : SLOPE * x;
}

__device__ __forceinline__ int load_idx(const void* p, long long i) {
    return g_is64 ? (int)((const long long*)p)[i] : ((const int*)p)[i];
}

// pack two floats as bf16x2: low half = a (even k), high half = b (odd k)
__device__ __forceinline__ uint32_t pack_bf16(float a, float b) {
    uint32_t r;
    asm("cvt.rn.bf16x2.f32 %0, %1, %2;" : "=r"(r) : "f"(b), "f"(a));
    return r;
}

__device__ __forceinline__ float bf16_hi_val(float x) {
    __nv_bfloat16 h = __float2bfloat16_rn(x);
    return __bfloat162float(h);
}

__device__ __forceinline__ void mma_bf16(float c[4], const uint32_t a[4],
                                         uint32_t b0, uint32_t b1) {
    asm volatile(
        "mma.sync.aligned.m16n8k16.row.col.f32.bf16.bf16.f32 "
        "{%0,%1,%2,%3}, {%4,%5,%6,%7}, {%8,%9}, {%0,%1,%2,%3};\n"
        : "+f"(c[0]), "+f"(c[1]), "+f"(c[2]), "+f"(c[3])
        : "r"(a[0]), "r"(a[1]), "r"(a[2]), "r"(a[3]), "r"(b0), "r"(b1));
}

// ---------------------------------------------------------------------------
// init: zero degrees, detect index dtype
// ---------------------------------------------------------------------------
__global__ void k_init(const int* __restrict__ eiw) {
    int i = blockIdx.x * blockDim.x + threadIdx.x;
    if (i < NN) g_deg[i] = 0;
    if (i == 0) {
        g_total = 0;
        int is64 = 1;
        #pragma unroll 1
        for (int t = 0; t < 64; t++) {
            if (eiw[2 * t + 1] != 0) { is64 = 0; break; }
        }
        g_is64 = is64;
    }
}

// ---------------------------------------------------------------------------
// CSR build (scan-free; per-dst ranges via global atomic cursor)
// ---------------------------------------------------------------------------
__global__ void k_hist(const void* __restrict__ ei) {
    int e = blockIdx.x * blockDim.x + threadIdx.x;
    if (e < EE) {
        int d = load_idx(ei, (long long)EE + e);
        if ((unsigned)d < NN) atomicAdd(&g_deg[d], 1);
    }
}

__global__ void k_alloc() {
    int i = blockIdx.x * blockDim.x + threadIdx.x;
    if (i < NN) {
        int dg = g_deg[i];
        int st = atomicAdd(&g_total, dg);
        g_start[i] = st;
        g_cur[i]   = st;
    }
}

__global__ void k_scatter(const void* __restrict__ ei) {
    int e = blockIdx.x * blockDim.x + threadIdx.x;
    if (e < EE) {
        int s = load_idx(ei, e);
        int d = load_idx(ei, (long long)EE + e);
        if ((unsigned)d < NN && (unsigned)s < NN) {
            int pos = atomicAdd(&g_cur[d], 1);
            g_csrc[pos] = s;
        }
    }
}

// ---------------------------------------------------------------------------
// 3xBF16 tensor-core GEMM: C[M,128] = A[M,128] @ B[128,128] (+bias)
// Block 128x128, 256 threads (8 warps, 2x4), warp tile 64x32, BK=16.
// A,B split into bf16 hi/lo (k-pairs packed bf16x2); acc += hh + hl + lh.
// m16n8k16 -> one k-step per 16-k chunk (half the MMAs of tf32x3).
// Optional fused epilogue: es/ed row-dots with asrc/adst.
// ---------------------------------------------------------------------------
#define PAD 136   // smem row stride (uint32): conflict-free fragment loads

template <bool FUSE_ESED>
__device__ __forceinline__ void mma_gemm_body(const float* __restrict__ A,
                                              const float* __restrict__ B,
                                              const float* __restrict__ bias,
                                              const float* __restrict__ asrc,
                                              const float* __restrict__ adst,
                                              float* __restrict__ C, int M) {
    __shared__ uint32_t Ah[8][PAD], Al[8][PAD];   // [k-pair][m]
    __shared__ uint32_t Bh[8][PAD], Bl[8][PAD];   // [k-pair][n]
    __shared__ float es_s[128], ed_s[128];

    const int tid  = threadIdx.x;
    const int warp = tid >> 5, lane = tid & 31;
    const int wm = warp >> 2, wn = warp & 3;   // 2 x 4 warp grid
    const int gid = lane >> 2, tig = lane & 3;
    const int brow = blockIdx.x * 128;

    if (FUSE_ESED && tid < 128) { es_s[tid] = 0.f; ed_s[tid] = 0.f; }

    // A loader: row = (tid&63) + 64*p, k-quad = (tid>>6)*4 -> pair rows kq/2, kq/2+1
    const int a_r  = tid & 63;
    const int a_kq = (tid >> 6) * 4;
    // B loader: pair-row bp = tid>>5 (0..7), n base = (tid&31)*4
    const int b_bp = tid >> 5;
    const int b_n  = (tid & 31) * 4;

    float acc[4][4][4];
    #pragma unroll
    for (int mt = 0; mt < 4; mt++)
        #pragma unroll
        for (int nt = 0; nt < 4; nt++)
            #pragma unroll
            for (int c = 0; c < 4; c++) acc[mt][nt][c] = 0.f;

    for (int kc = 0; kc < 128; kc += 16) {
        // ---- stage A (bf16 hi/lo split), k-pairs, transposed to [kpair][m]
        #pragma unroll
        for (int p = 0; p < 2; p++) {
            int r = a_r + 64 * p;
            int grow = brow + r;
            float4 v = (grow < M) ? *(const float4*)&A[(size_t)grow * 128 + kc + a_kq]
                                  : make_float4(0.f, 0.f, 0.f, 0.f);
            float f[4] = {v.x, v.y, v.z, v.w};
            float h[4], l[4];
            #pragma unroll
            for (int i = 0; i < 4; i++) {
                h[i] = bf16_hi_val(f[i]);
                l[i] = f[i] - h[i];
            }
            Ah[a_kq / 2][r]     = pack_bf16(h[0], h[1]);
            Ah[a_kq / 2 + 1][r] = pack_bf16(h[2], h[3]);
            Al[a_kq / 2][r]     = pack_bf16(l[0], l[1]);
            Al[a_kq / 2 + 1][r] = pack_bf16(l[2], l[3]);
        }
        // ---- stage B: pairs across two k rows, [kpair][n]
        {
            const float* B0 = &B[(size_t)(kc + 2 * b_bp) * 128 + b_n];
            float4 r0 = *(const float4*)B0;
            float4 r1 = *(const float4*)(B0 + 128);
            float f0[4] = {r0.x, r0.y, r0.z, r0.w};
            float f1[4] = {r1.x, r1.y, r1.z, r1.w};
            uint4 hq, lq;
            uint32_t* hp_ = (uint32_t*)&hq;
            uint32_t* lp_ = (uint32_t*)&lq;
            #pragma unroll
            for (int i = 0; i < 4; i++) {
                float h0 = bf16_hi_val(f0[i]), l0 = f0[i] - h0;
                float h1 = bf16_hi_val(f1[i]), l1 = f1[i] - h1;
                hp_[i] = pack_bf16(h0, h1);
                lp_[i] = pack_bf16(l0, l1);
            }
            *(uint4*)&Bh[b_bp][b_n] = hq;
            *(uint4*)&Bl[b_bp][b_n] = lq;
        }
        __syncthreads();

        // single k16 step per chunk
        {
            uint32_t ah[4][4], al[4][4];
            #pragma unroll
            for (int mt = 0; mt < 4; mt++) {
                int m0 = wm * 64 + mt * 16 + gid;
                ah[mt][0] = Ah[tig][m0];     ah[mt][1] = Ah[tig][m0 + 8];
                ah[mt][2] = Ah[tig + 4][m0]; ah[mt][3] = Ah[tig + 4][m0 + 8];
                al[mt][0] = Al[tig][m0];     al[mt][1] = Al[tig][m0 + 8];
                al[mt][2] = Al[tig + 4][m0]; al[mt][3] = Al[tig + 4][m0 + 8];
            }
            #pragma unroll
            for (int nt = 0; nt < 4; nt++) {
                int n0 = wn * 32 + nt * 8 + gid;
                uint32_t bh0 = Bh[tig][n0], bh1 = Bh[tig + 4][n0];
                uint32_t bl0 = Bl[tig][n0], bl1 = Bl[tig + 4][n0];
                #pragma unroll
                for (int mt = 0; mt < 4; mt++) {
                    mma_bf16(acc[mt][nt], ah[mt], bh0, bh1);  // hi*hi
                    mma_bf16(acc[mt][nt], ah[mt], bl0, bl1);  // hi*lo
                    mma_bf16(acc[mt][nt], al[mt], bh0, bh1);  // lo*hi
                }
            }
        }
        __syncthreads();
    }

    // attention-vector values for this thread's columns
    float as_v[4][2], ad_v[4][2];
    if (FUSE_ESED) {
        #pragma unroll
        for (int nt = 0; nt < 4; nt++) {
            int c0 = wn * 32 + nt * 8 + 2 * tig;
            as_v[nt][0] = asrc[c0]; as_v[nt][1] = asrc[c0 + 1];
            ad_v[nt][0] = adst[c0]; ad_v[nt][1] = adst[c0 + 1];
        }
    }

    // epilogue: store C (+bias) and accumulate es/ed partials
    #pragma unroll
    for (int mt = 0; mt < 4; mt++) {
        int r0 = brow + wm * 64 + mt * 16 + gid;
        float pe0 = 0.f, pe1 = 0.f, pd0 = 0.f, pd1 = 0.f;
        #pragma unroll
        for (int nt = 0; nt < 4; nt++) {
            int c0 = wn * 32 + nt * 8 + 2 * tig;
            float b0v = bias ? bias[c0]     : 0.f;
            float b1v = bias ? bias[c0 + 1] : 0.f;
            float v00 = acc[mt][nt][0] + b0v, v01 = acc[mt][nt][1] + b1v;
            float v10 = acc[mt][nt][2] + b0v, v11 = acc[mt][nt][3] + b1v;
            if (r0 < M)     *(float2*)&C[(size_t)r0 * 128 + c0]       = make_float2(v00, v01);
            if (r0 + 8 < M) *(float2*)&C[(size_t)(r0 + 8) * 128 + c0] = make_float2(v10, v11);
            if (FUSE_ESED) {
                pe0 += v00 * as_v[nt][0] + v01 * as_v[nt][1];
                pe1 += v10 * as_v[nt][0] + v11 * as_v[nt][1];
                pd0 += v00 * ad_v[nt][0] + v01 * ad_v[nt][1];
                pd1 += v10 * ad_v[nt][0] + v11 * ad_v[nt][1];
            }
        }
        if (FUSE_ESED) {
            #pragma unroll
            for (int o = 1; o <= 2; o <<= 1) {
                pe0 += __shfl_xor_sync(0xffffffffu, pe0, o);
                pe1 += __shfl_xor_sync(0xffffffffu, pe1, o);
                pd0 += __shfl_xor_sync(0xffffffffu, pd0, o);
                pd1 += __shfl_xor_sync(0xffffffffu, pd1, o);
            }
            if (tig == 0) {
                int lr = wm * 64 + mt * 16 + gid;
                atomicAdd(&es_s[lr], pe0);     atomicAdd(&es_s[lr + 8], pe1);
                atomicAdd(&ed_s[lr], pd0);     atomicAdd(&ed_s[lr + 8], pd1);
            }
        }
    }

    if (FUSE_ESED) {
        __syncthreads();
        if (tid < 128 && brow + tid < M) {
            g_es[brow + tid] = es_s[tid];
            g_ed[brow + tid] = ed_s[tid];
        }
    }
}

__global__ void __launch_bounds__(256) k_mma_x(const float* __restrict__ A,
                                               const float* __restrict__ B,
                                               const float* __restrict__ bias) {
    mma_gemm_body<false>(A, B, bias, nullptr, nullptr, g_h, NN);
}

__global__ void __launch_bounds__(256) k_mma_h(const float* __restrict__ B,
                                               const float* __restrict__ asrc,
                                               const float* __restrict__ adst) {
    mma_gemm_body<true>(g_h, B, nullptr, asrc, adst, g_hp, NN);
}

// ---------------------------------------------------------------------------
// GAT aggregation (warp per destination node)
// ---------------------------------------------------------------------------
__global__ void k_gat_aggr(const float* __restrict__ bg) {
    int warp = (blockIdx.x * blockDim.x + threadIdx.x) >> 5;
    int lane = threadIdx.x & 31;
    if (warp >= NN) return;
    const int d = warp;
    const int lo = g_start[d], hi = lo + g_deg[d];
    const float es_d = g_es[d], ed_d = g_ed[d];
    const float e_self = leaky(es_d + ed_d);

    // pass 1: edge scores + segment max
    float m = e_self;
    for (int j = lo + lane; j < hi; j += 32) {
        int s = g_csrc[j];
        float e = leaky(g_es[s] + ed_d);
        g_ee[j] = e;
        m = fmaxf(m, e);
    }
    #pragma unroll
    for (int o = 16; o; o >>= 1) m = fmaxf(m, __shfl_xor_sync(0xffffffffu, m, o));

    const float4* hp4 = (const float4*)g_hp;
    float4* h4 = (float4*)g_h;

    // pass 2: unnormalized weighted sum + z
    float ex_self = expf(e_self - m);
    float z = ex_self;
    float4 v = hp4[(size_t)d * 32 + lane];
    float4 acc;
    acc.x = ex_self * v.x; acc.y = ex_self * v.y;
    acc.z = ex_self * v.z; acc.w = ex_self * v.w;

    for (int j = lo; j < hi; ++j) {
        int s = g_csrc[j];
        float ex = expf(g_ee[j] - m);
        z += ex;
        float4 w = hp4[(size_t)s * 32 + lane];
        acc.x = fmaf(ex, w.x, acc.x);
        acc.y = fmaf(ex, w.y, acc.y);
        acc.z = fmaf(ex, w.z, acc.z);
        acc.w = fmaf(ex, w.w, acc.w);
    }
    const float invz = 1.0f / z;

    float4 b = ((const float4*)bg)[lane];
    float4 hin = h4[(size_t)d * 32 + lane];
    float4 o;
    o.x = fmaxf(fmaf(acc.x, invz, b.x), 0.f) + hin.x;
    o.y = fmaxf(fmaf(acc.y, invz, b.y), 0.f) + hin.y;
    o.z = fmaxf(fmaf(acc.z, invz, b.z), 0.f) + hin.z;
    o.w = fmaxf(fmaf(acc.w, invz, b.w), 0.f) + hin.w;
    h4[(size_t)d * 32 + lane] = o;
}

// ---------------------------------------------------------------------------
// Fused pool + final projection: block per graph (batch sorted)
// ---------------------------------------------------------------------------
__global__ void k_poolfinal(const void* __restrict__ batch,
                            const float* __restrict__ W2,
                            const float* __restrict__ b2,
                            float* __restrict__ out) {
    __shared__ float ps[128];
    __shared__ int s_lo, s_hi;
    const int g = blockIdx.x;
    const int tid = threadIdx.x;   // 128 threads, one per feature column
    if (tid == 0) {
        int lo = 0, hi = NN;
        while (lo < hi) { int mid = (lo + hi) >> 1; if (load_idx(batch, mid) < g) lo = mid + 1; else hi = mid; }
        s_lo = lo;
        lo = 0; hi = NN;
        int g1 = g + 1;
        while (lo < hi) { int mid = (lo + hi) >> 1; if (load_idx(batch, mid) < g1) lo = mid + 1; else hi = mid; }
        s_hi = lo;
    }
    __syncthreads();
    float acc = 0.f;
    for (int i = s_lo; i < s_hi; ++i) acc += g_h[(size_t)i * 128 + tid];
    ps[tid] = acc;
    __syncthreads();
    if (tid < 64) {
        float o = b2[tid];
        #pragma unroll 8
        for (int k = 0; k < 128; ++k)
            o = fmaf(ps[k], W2[k * 64 + tid], o);
        out[g * 64 + tid] = o;
    }
}

// ---------------------------------------------------------------------------
// Launch
// ---------------------------------------------------------------------------
extern "C" void kernel_launch(void* const* d_in, const int* in_sizes, int n_in,
                              void* d_out, int out_size) {
    const float* x     = (const float*)d_in[0];
    const void*  ei    = d_in[1];
    const void*  batch = d_in[2];
    const float* W1    = (const float*)d_in[3];
    const float* b1    = (const float*)d_in[4];
    const float* Wg    = (const float*)d_in[5];
    const float* asrc  = (const float*)d_in[6];
    const float* adst  = (const float*)d_in[7];
    const float* bg    = (const float*)d_in[8];
    const float* W2    = (const float*)d_in[9];
    const float* b2    = (const float*)d_in[10];
    float*       out   = (float*)d_out;

    k_init<<<(NN + 255) / 256, 256>>>((const int*)ei);
    k_hist<<<(EE + 255) / 256, 256>>>(ei);
    k_alloc<<<(NN + 255) / 256, 256>>>();
    k_scatter<<<(EE + 255) / 256, 256>>>(ei);

    const int gemm_blocks = (NN + 127) / 128;
    const int node_warp_blocks = (NN * 32 + 255) / 256;

    k_mma_x<<<gemm_blocks, 256>>>(x, W1, b1);

    for (int l = 0; l < NLAYERS; ++l) {
        k_mma_h<<<gemm_blocks, 256>>>(Wg + (size_t)l * 128 * 128,
                                      asrc + l * 128, adst + l * 128);
        k_gat_aggr<<<node_warp_blocks, 256>>>(bg + l * 128);
    }

    k_poolfinal<<<NG, 128>>>(batch, W2, b2, out);
}